// round 2
// baseline (speedup 1.0000x reference)
#include <cuda_runtime.h>
#include <cuda_fp16.h>
#include <cuda_bf16.h>
#include <mma.h>
#include <math.h>
#include <stdint.h>

using namespace nvcuda;

#define S_LEN 2048
#define D_DIM 4096
#define H_NUM 32
#define HD    128
#define KDIM  4096

// ---------------- static scratch (allocation-free rule) ----------------
__device__ int8_t g_x8[S_LEN * D_DIM];            // quantized hidden, int8
__device__ int8_t g_w8[4][D_DIM * D_DIM];         // wq,wk,wv,wo as int8
__device__ int    g_pint[3][S_LEN * D_DIM];       // raw int32 q/k/v projections; [0] reused for o-proj
__device__ int8_t g_q8[H_NUM * S_LEN * HD];       // roped+quantized Q  [H,S,HD]
__device__ int8_t g_k8[H_NUM * S_LEN * HD];       // roped+quantized K  [H,S,HD]
__device__ __half g_vh[H_NUM * S_LEN * HD];       // quantized V (int vals in half) [H,S,HD]
__device__ int8_t g_oq[S_LEN * D_DIM];            // quantized attention out [S,D]
__device__ float2 g_rope[S_LEN * 64];             // (cos,sin) table

// ---------------- helpers ----------------
__device__ __forceinline__ void cp_async16(void* smem, const void* gmem) {
    unsigned saddr = (unsigned)__cvta_generic_to_shared(smem);
    asm volatile("cp.async.cg.shared.global [%0], [%1], 16;\n" :: "r"(saddr), "l"(gmem));
}
__device__ __forceinline__ void cp_commit() { asm volatile("cp.async.commit_group;\n"); }
__device__ __forceinline__ void cp_wait0()  { asm volatile("cp.async.wait_group 0;\n"); }
__device__ __forceinline__ int clampi(int v, int lo, int hi) { return max(lo, min(hi, v)); }

// ---------------- elementwise kernels ----------------
__global__ void quant_x_kernel(const float* __restrict__ hs) {
    int idx = blockIdx.x * blockDim.x + threadIdx.x;
    if (idx >= S_LEN * D_DIM) return;
    int q = clampi(__float2int_rn(__fdiv_rn(hs[idx], 0.1f)), -128, 127);
    g_x8[idx] = (int8_t)q;
}

__global__ void convert_w_kernel(const float* __restrict__ wq, const float* __restrict__ wk,
                                 const float* __restrict__ wv, const float* __restrict__ wo) {
    int idx = blockIdx.x * blockDim.x + threadIdx.x;
    int z = blockIdx.y;
    if (idx >= D_DIM * D_DIM) return;
    const float* src = (z == 0) ? wq : (z == 1) ? wk : (z == 2) ? wv : wo;
    g_w8[z][idx] = (int8_t)__float2int_rn(src[idx]);
}

__global__ void rope_table_kernel(const int* __restrict__ pos) {
    int idx = blockIdx.x * blockDim.x + threadIdx.x;
    if (idx >= S_LEN * 64) return;
    int s = idx >> 6, i = idx & 63;
    // e = (2*i)/128 exact; inv_freq = fl32(1.0f / fl32(10000^e))  (matches jax fp32 graph)
    float e = (float)(2 * i) * (1.0f / 128.0f);
    float powf32 = (float)pow(10000.0, (double)e);   // correctly-rounded f32
    float invf = 1.0f / powf32;                      // fp32 divide like reference
    float ang = (float)pos[s] * invf;                // fp32 multiply
    double a = (double)ang;
    g_rope[idx] = make_float2((float)cos(a), (float)sin(a));
}

__global__ void ropequant_kernel(const float* __restrict__ sq, const float* __restrict__ sk,
                                 const float* __restrict__ sv) {
    int idx = blockIdx.x * blockDim.x + threadIdx.x;
    if (idx >= S_LEN * D_DIM) return;
    int s = idx >> 12, o = idx & (D_DIM - 1);
    int h = o >> 7, j = o & 127;
    float2 cs = g_rope[(s << 6) + (j & 63)];
    int o2 = (h << 7) + ((j < 64) ? (j + 64) : (j - 64));
    float sign = (j < 64) ? -1.0f : 1.0f;
    int base = s * D_DIM;
    int dsti = (h * S_LEN + s) * HD + j;
    {   // Q: dequant, rope, requant
        float sa = __fmul_rn(0.1f, sq[o]);
        float sb = __fmul_rn(0.1f, sq[o2]);
        float a = __fmul_rn((float)g_pint[0][base + o], sa);
        float b = __fmul_rn((float)g_pint[0][base + o2], sb) * sign;
        float r = __fadd_rn(__fmul_rn(a, cs.x), __fmul_rn(b, cs.y));
        g_q8[dsti] = (int8_t)clampi(__float2int_rn(__fdiv_rn(r, 0.1f)), -128, 127);
    }
    {   // K
        float sa = __fmul_rn(0.1f, sk[o]);
        float sb = __fmul_rn(0.1f, sk[o2]);
        float a = __fmul_rn((float)g_pint[1][base + o], sa);
        float b = __fmul_rn((float)g_pint[1][base + o2], sb) * sign;
        float r = __fadd_rn(__fmul_rn(a, cs.x), __fmul_rn(b, cs.y));
        g_k8[dsti] = (int8_t)clampi(__float2int_rn(__fdiv_rn(r, 0.1f)), -128, 127);
    }
    {   // V (no rope)
        float a = __fmul_rn((float)g_pint[2][base + o], __fmul_rn(0.1f, sv[o]));
        int q = clampi(__float2int_rn(__fdiv_rn(a, 0.1f)), -128, 127);
        g_vh[dsti] = __float2half_rn((float)q);
    }
}

__global__ void final_kernel(const float* __restrict__ so, float* __restrict__ out) {
    int idx = blockIdx.x * blockDim.x + threadIdx.x;
    if (idx >= S_LEN * D_DIM) return;
    out[idx] = __fmul_rn((float)g_pint[0][idx], __fmul_rn(0.1f, so[idx & (D_DIM - 1)]));
}

// ---------------- int8 GEMM (s8 x s8 -> s32), C[M,N] = A[M,K] * B[N,K]^T ----------------
#define GBM 128
#define GBN 128
#define GBK 64
#define GLD 80   // padded smem row stride (bytes)

__global__ __launch_bounds__(128) void gemm_s8_kernel(int mode) {
    __shared__ __align__(16) int8_t As[2][GBM * GLD];
    __shared__ __align__(16) int8_t Bs[2][GBN * GLD];
    const int8_t* A; const int8_t* B; int* C;
    if (mode == 0) { A = g_x8; B = g_w8[blockIdx.z]; C = g_pint[blockIdx.z]; }
    else           { A = g_oq; B = g_w8[3];          C = g_pint[0]; }
    const int m0 = blockIdx.y * GBM, n0 = blockIdx.x * GBN;
    int tid = threadIdx.x;
    int w = tid >> 5;
    int wm = w & 1, wn = w >> 1;

    wmma::fragment<wmma::accumulator, 16, 16, 16, int> acc[4][4];
    #pragma unroll
    for (int i = 0; i < 4; i++)
        #pragma unroll
        for (int j = 0; j < 4; j++) wmma::fill_fragment(acc[i][j], 0);

    const int KT = KDIM / GBK;
    #pragma unroll
    for (int c = tid; c < 512; c += 128) {
        int r = c >> 2, off = (c & 3) << 4;
        cp_async16(&As[0][r * GLD + off], A + (size_t)(m0 + r) * KDIM + off);
        cp_async16(&Bs[0][r * GLD + off], B + (size_t)(n0 + r) * KDIM + off);
    }
    cp_commit();

    for (int kt = 0; kt < KT; kt++) {
        int buf = kt & 1;
        cp_wait0();
        __syncthreads();
        if (kt + 1 < KT) {
            int k0 = (kt + 1) * GBK;
            #pragma unroll
            for (int c = tid; c < 512; c += 128) {
                int r = c >> 2, off = (c & 3) << 4;
                cp_async16(&As[buf ^ 1][r * GLD + off], A + (size_t)(m0 + r) * KDIM + k0 + off);
                cp_async16(&Bs[buf ^ 1][r * GLD + off], B + (size_t)(n0 + r) * KDIM + k0 + off);
            }
            cp_commit();
        }
        #pragma unroll
        for (int ks = 0; ks < 4; ks++) {
            wmma::fragment<wmma::matrix_a, 16, 16, 16, signed char, wmma::row_major> af[4];
            wmma::fragment<wmma::matrix_b, 16, 16, 16, signed char, wmma::col_major> bf[4];
            #pragma unroll
            for (int i = 0; i < 4; i++)
                wmma::load_matrix_sync(af[i], (const signed char*)&As[buf][(wm * 64 + i * 16) * GLD + ks * 16], GLD);
            #pragma unroll
            for (int j = 0; j < 4; j++)
                wmma::load_matrix_sync(bf[j], (const signed char*)&Bs[buf][(wn * 64 + j * 16) * GLD + ks * 16], GLD);
            #pragma unroll
            for (int i = 0; i < 4; i++)
                #pragma unroll
                for (int j = 0; j < 4; j++)
                    wmma::mma_sync(acc[i][j], af[i], bf[j], acc[i][j]);
        }
        __syncthreads();
    }
    #pragma unroll
    for (int i = 0; i < 4; i++)
        #pragma unroll
        for (int j = 0; j < 4; j++)
            wmma::store_matrix_sync(C + (size_t)(m0 + wm * 64 + i * 16) * D_DIM + (n0 + wn * 64 + j * 16),
                                    acc[i][j], D_DIM, wmma::mem_row_major);
}

// ---------------- causal flash attention ----------------
#define QLD 144   // int8 row stride (bytes)
#define VLD 136   // half row stride (elements)
#define SLD 72    // score / P row stride (elements)
#define OLD 132   // O row stride (floats)

// dynamic smem layout offsets (bytes)
#define OFF_Q  0
#define OFF_K  9216
#define OFF_V  18432
#define OFF_SI 35840
#define OFF_PH 54272
#define OFF_PL 63488
#define OFF_O  72704
#define OFF_M  106496
#define OFF_L  106752
#define SMEM_ATTN 107008

__global__ __launch_bounds__(256) void attn_kernel() {
    extern __shared__ __align__(16) char sm[];
    int8_t* Qs = (int8_t*)(sm + OFF_Q);
    int8_t* Ks = (int8_t*)(sm + OFF_K);
    __half* Vs = (__half*)(sm + OFF_V);
    int*    Si = (int*)(sm + OFF_SI);
    __half* Ph = (__half*)(sm + OFF_PH);
    __half* Pl = (__half*)(sm + OFF_PL);
    float*  Os = (float*)(sm + OFF_O);
    float*  m_s = (float*)(sm + OFF_M);
    float*  l_s = (float*)(sm + OFF_L);

    int qtile = gridDim.x - 1 - blockIdx.x;    // heavy tiles first
    int h = blockIdx.y;
    int tid = threadIdx.x;
    int w = tid >> 5;
    const float NEGINF = __int_as_float(0xff800000);

    {   // load Q tile (64 x 128 int8)
        const int8_t* Qg = g_q8 + (size_t)(h * S_LEN + qtile * 64) * HD;
        #pragma unroll
        for (int c = tid; c < 512; c += 256) {
            int r = c >> 3, off = (c & 7) << 4;
            *(int4*)(Qs + r * QLD + off) = *(const int4*)(Qg + r * HD + off);
        }
    }
    for (int i = tid; i < 64 * OLD; i += 256) Os[i] = 0.0f;
    if (tid < 64) { m_s[tid] = -1e30f; l_s[tid] = 0.0f; }

    int row = tid >> 2;
    int qd  = tid & 3;
    const float SC = (float)((double)0.1f * (double)0.1f / 11.313708498984760390);  // 0.01/sqrt(128)

    for (int t = 0; t <= qtile; t++) {
        __syncthreads();
        // load K (64x128 s8) and V (64x128 half)
        const int8_t* Kg = g_k8 + (size_t)(h * S_LEN + t * 64) * HD;
        #pragma unroll
        for (int c = tid; c < 512; c += 256) {
            int r = c >> 3, off = (c & 7) << 4;
            *(int4*)(Ks + r * QLD + off) = *(const int4*)(Kg + r * HD + off);
        }
        const __half* Vg = g_vh + (size_t)(h * S_LEN + t * 64) * HD;
        #pragma unroll
        for (int c = tid; c < 1024; c += 256) {
            int r = c >> 4, off = (c & 15) << 4;
            *(int4*)((char*)Vs + r * (VLD * 2) + off) = *(const int4*)((const char*)(Vg + r * HD) + off);
        }
        __syncthreads();

        // S = Q * K^T  (s8 -> exact s32). 8 warps: 4 m-strips x 2 n-groups(2 frags)
        {
            int wm = w & 3;
            int wnb = (w >> 2) << 1;
            wmma::fragment<wmma::accumulator, 16, 16, 16, int> sacc[2];
            wmma::fill_fragment(sacc[0], 0);
            wmma::fill_fragment(sacc[1], 0);
            #pragma unroll
            for (int k = 0; k < 8; k++) {
                wmma::fragment<wmma::matrix_a, 16, 16, 16, signed char, wmma::row_major> aq;
                wmma::load_matrix_sync(aq, (const signed char*)(Qs + (wm * 16) * QLD + k * 16), QLD);
                #pragma unroll
                for (int n = 0; n < 2; n++) {
                    wmma::fragment<wmma::matrix_b, 16, 16, 16, signed char, wmma::col_major> bk;
                    wmma::load_matrix_sync(bk, (const signed char*)(Ks + ((wnb + n) * 16) * QLD + k * 16), QLD);
                    wmma::mma_sync(sacc[n], aq, bk, sacc[n]);
                }
            }
            wmma::store_matrix_sync(Si + (wm * 16) * SLD + wnb * 16,       sacc[0], SLD, wmma::mem_row_major);
            wmma::store_matrix_sync(Si + (wm * 16) * SLD + (wnb + 1) * 16, sacc[1], SLD, wmma::mem_row_major);
        }
        __syncthreads();

        // online softmax: 4 lanes per row, 16 cols each
        {
            bool diag = (t == qtile);
            float vals[16];
            float mloc = NEGINF;
            #pragma unroll
            for (int jj = 0; jj < 16; jj++) {
                int j = qd * 16 + jj;
                float v = (diag && j > row) ? NEGINF : (float)Si[row * SLD + j] * SC;
                vals[jj] = v;
                mloc = fmaxf(mloc, v);
            }
            mloc = fmaxf(mloc, __shfl_xor_sync(0xffffffffu, mloc, 1));
            mloc = fmaxf(mloc, __shfl_xor_sync(0xffffffffu, mloc, 2));
            float mold = m_s[row];
            float mnew = fmaxf(mold, mloc);
            float alpha = expf(mold - mnew);
            float psum = 0.0f;
            #pragma unroll
            for (int jj = 0; jj < 16; jj++) {
                float p = expf(vals[jj] - mnew);
                psum += p;
                __half ph = __float2half_rn(p);
                Ph[row * SLD + qd * 16 + jj] = ph;
                Pl[row * SLD + qd * 16 + jj] = __float2half_rn(p - __half2float(ph));
            }
            psum += __shfl_xor_sync(0xffffffffu, psum, 1);
            psum += __shfl_xor_sync(0xffffffffu, psum, 2);
            if (qd == 0) {
                m_s[row] = mnew;
                l_s[row] = l_s[row] * alpha + psum;
            }
            if (alpha != 1.0f) {
                #pragma unroll
                for (int c = 0; c < 32; c++)
                    Os[row * OLD + qd * 32 + c] *= alpha;
            }
        }
        __syncthreads();

        // O += (Ph + Pl) * V  (split fp16 -> near-fp32 exact). 8 warps: 4 m-strips x 2 col-groups of 64
        {
            int wm = w & 3;
            int wnb = (w >> 2) << 2;   // 4 col-frags of 16
            wmma::fragment<wmma::accumulator, 16, 16, 16, float> oacc[4];
            #pragma unroll
            for (int n = 0; n < 4; n++)
                wmma::load_matrix_sync(oacc[n], Os + (wm * 16) * OLD + (wnb + n) * 16, OLD, wmma::mem_row_major);
            #pragma unroll
            for (int k = 0; k < 4; k++) {
                wmma::fragment<wmma::matrix_a, 16, 16, 16, __half, wmma::row_major> aph, apl;
                wmma::load_matrix_sync(aph, Ph + (wm * 16) * SLD + k * 16, SLD);
                wmma::load_matrix_sync(apl, Pl + (wm * 16) * SLD + k * 16, SLD);
                #pragma unroll
                for (int n = 0; n < 4; n++) {
                    wmma::fragment<wmma::matrix_b, 16, 16, 16, __half, wmma::row_major> bv;
                    wmma::load_matrix_sync(bv, Vs + (k * 16) * VLD + (wnb + n) * 16, VLD);
                    wmma::mma_sync(oacc[n], aph, bv, oacc[n]);
                    wmma::mma_sync(oacc[n], apl, bv, oacc[n]);
                }
            }
            #pragma unroll
            for (int n = 0; n < 4; n++)
                wmma::store_matrix_sync(Os + (wm * 16) * OLD + (wnb + n) * 16, oacc[n], OLD, wmma::mem_row_major);
        }
    }
    __syncthreads();

    // epilogue: out = (Os/l)*0.1 ; quantize round(x/0.1), clamp -127..127
    {
        float linv = l_s[row];
        int s_glob = qtile * 64 + row;
        int8_t* dst = g_oq + (size_t)s_glob * D_DIM + h * HD;
        #pragma unroll
        for (int c = 0; c < 32; c++) {
            int col = qd * 32 + c;
            float x = __fmul_rn(__fdiv_rn(Os[row * OLD + col], linv), 0.1f);
            dst[col] = (int8_t)clampi(__float2int_rn(__fdiv_rn(x, 0.1f)), -127, 127);
        }
    }
}

// ---------------- launch ----------------
extern "C" void kernel_launch(void* const* d_in, const int* in_sizes, int n_in,
                              void* d_out, int out_size) {
    const float* hs = (const float*)d_in[0];
    const float* wq = (const float*)d_in[1];
    const float* wk = (const float*)d_in[2];
    const float* wv = (const float*)d_in[3];
    const float* wo = (const float*)d_in[4];
    const float* sq = (const float*)d_in[5];
    const float* sk = (const float*)d_in[6];
    const float* sv = (const float*)d_in[7];
    const float* so = (const float*)d_in[8];
    const int*   pos = (const int*)d_in[10];
    float* out = (float*)d_out;

    cudaFuncSetAttribute(attn_kernel, cudaFuncAttributeMaxDynamicSharedMemorySize, SMEM_ATTN);

    quant_x_kernel<<<(S_LEN * D_DIM + 255) / 256, 256>>>(hs);
    convert_w_kernel<<<dim3((D_DIM * D_DIM + 255) / 256, 4), 256>>>(wq, wk, wv, wo);
    rope_table_kernel<<<(S_LEN * 64 + 255) / 256, 256>>>(pos);

    gemm_s8_kernel<<<dim3(D_DIM / GBN, S_LEN / GBM, 3), 128>>>(0);   // QKV projections
    ropequant_kernel<<<(S_LEN * D_DIM + 255) / 256, 256>>>(sq, sk, sv);

    attn_kernel<<<dim3(S_LEN / 64, H_NUM), 256, SMEM_ATTN>>>();

    gemm_s8_kernel<<<dim3(D_DIM / GBN, S_LEN / GBM, 1), 128>>>(1);   // o-proj
    final_kernel<<<(S_LEN * D_DIM + 255) / 256, 256>>>(so, out);
}

// round 4
// speedup vs baseline: 4.1353x; 4.1353x over previous
#include <cuda_runtime.h>
#include <cuda_fp16.h>
#include <cuda_bf16.h>
#include <mma.h>
#include <math.h>
#include <stdint.h>

using namespace nvcuda;

#define S_LEN 2048
#define D_DIM 4096
#define H_NUM 32
#define HD    128
#define KDIM  4096

// Arch-specific feature gate: tcgen05 only exists under 'a'/'f' targets.
#if defined(__CUDA_ARCH__) && (defined(__CUDA_ARCH_FEAT_SM103_ALL) || defined(__CUDA_ARCH_FEAT_SM100_ALL) || defined(__CUDA_ARCH_SPECIFIC__) || defined(__CUDA_ARCH_FAMILY_SPECIFIC__))
#define USE_TC 1
#else
#define USE_TC 0
#endif

// ---------------- static scratch (allocation-free rule) ----------------
__device__ int8_t g_x8[S_LEN * D_DIM];              // quantized hidden, int8 linear (wmma path)
__device__ int8_t g_w8[4][D_DIM * D_DIM];           // weights int8 linear (wmma path)
__device__ __nv_bfloat16 g_xa[S_LEN * D_DIM];       // quantized hidden, bf16 SW128-tiled (tc path)
__device__ __nv_bfloat16 g_wb[4][D_DIM * D_DIM];    // weights bf16 SW128-tiled (tc path)
__device__ __nv_bfloat16 g_oa[S_LEN * D_DIM];       // attn out bf16 SW128-tiled (tc path)
__device__ int    g_pint[3][S_LEN * D_DIM];         // raw int32 projections; [0] reused for o-proj
__device__ int8_t g_q8[H_NUM * S_LEN * HD];         // roped+quantized Q  [H,S,HD]
__device__ int8_t g_k8[H_NUM * S_LEN * HD];         // roped+quantized K  [H,S,HD]
__device__ __half g_vh[H_NUM * S_LEN * HD];         // quantized V (int vals in half) [H,S,HD]
__device__ int8_t g_oq[S_LEN * D_DIM];              // quantized attention out [S,D] (wmma path)
__device__ float2 g_rope[S_LEN * 64];               // (cos,sin) table

// ---------------- helpers ----------------
__device__ __forceinline__ void cp_async16(void* smem, const void* gmem) {
    unsigned saddr = (unsigned)__cvta_generic_to_shared(smem);
    asm volatile("cp.async.cg.shared.global [%0], [%1], 16;\n" :: "r"(saddr), "l"(gmem));
}
__device__ __forceinline__ void cp_commit() { asm volatile("cp.async.commit_group;\n"); }
__device__ __forceinline__ void cp_wait0()  { asm volatile("cp.async.wait_group 0;\n"); }
__device__ __forceinline__ int clampi(int v, int lo, int hi) { return max(lo, min(hi, v)); }

// swizzled byte offset inside a [rows x 128B] SW128 tile for (row r, bf16 col c<64)
__device__ __forceinline__ uint32_t sw_off(int r, int c) {
    return (uint32_t)((r * 128 + c * 2) ^ ((r & 7) << 4));
}

#if USE_TC
__device__ __forceinline__ uint32_t smem_u32(const void* p) {
    uint32_t a;
    asm("{ .reg .u64 t; cvta.to.shared.u64 t, %1; cvt.u32.u64 %0, t; }" : "=r"(a) : "l"(p));
    return a;
}
#define MBARRIER_INIT(addr, cnt) \
    asm volatile("mbarrier.init.shared.b64 [%0], %1;" :: "r"((uint32_t)(addr)), "r"((uint32_t)(cnt)) : "memory")
#define MBARRIER_EXPECT_TX(addr, bytes) \
    asm volatile("mbarrier.arrive.expect_tx.shared.b64 _, [%0], %1;" :: "r"((uint32_t)(addr)), "r"((uint32_t)(bytes)) : "memory")
#define MBARRIER_WAIT_PARITY(addr, ph) do {                                   \
    uint32_t _m = (uint32_t)(addr); uint32_t _p = (uint32_t)(ph);             \
    asm volatile("{\n\t.reg .pred P1;\n\t"                                    \
        "WL_%=:\n\t"                                                          \
        "mbarrier.try_wait.parity.acquire.cta.shared::cta.b64 P1, [%0], %1, 0x989680;\n\t" \
        "@P1 bra.uni WD_%=;\n\t"                                              \
        "bra.uni WL_%=;\n\t"                                                  \
        "WD_%=:\n\t}"                                                         \
        :: "r"(_m), "r"(_p) : "memory");                                      \
} while (0)
#define TCGEN05_ALLOC(sma, n) \
    asm volatile("tcgen05.alloc.cta_group::1.sync.aligned.shared::cta.b32 [%0], %1;" \
        :: "r"((uint32_t)(sma)), "r"((uint32_t)(n)) : "memory")
#define TCGEN05_DEALLOC(tm, n) \
    asm volatile("tcgen05.dealloc.cta_group::1.sync.aligned.b32 %0, %1;" :: "r"(tm), "r"((uint32_t)(n)))
#define TCGEN05_RELINQ() \
    asm volatile("tcgen05.relinquish_alloc_permit.cta_group::1.sync.aligned;")
#define TCGEN05_COMMIT(mb) \
    asm volatile("tcgen05.commit.cta_group::1.mbarrier::arrive::one.shared::cluster.b64 [%0];" \
        :: "r"((uint32_t)(mb)) : "memory")
#define TCGEN05_FENCE_AFTER() asm volatile("tcgen05.fence::after_thread_sync;" ::: "memory")
#define TCGEN05_WAIT_LD()     asm volatile("tcgen05.wait::ld.sync.aligned;" ::: "memory")
#define TCGEN05_LD_X32(r, tma) \
    asm volatile("tcgen05.ld.sync.aligned.32x32b.x32.b32 " \
        "{%0,%1,%2,%3,%4,%5,%6,%7,%8,%9,%10,%11,%12,%13,%14,%15," \
        "%16,%17,%18,%19,%20,%21,%22,%23,%24,%25,%26,%27,%28,%29,%30,%31}, [%32];" \
        : "=r"((r)[0]), "=r"((r)[1]), "=r"((r)[2]), "=r"((r)[3]),   \
          "=r"((r)[4]), "=r"((r)[5]), "=r"((r)[6]), "=r"((r)[7]),   \
          "=r"((r)[8]), "=r"((r)[9]), "=r"((r)[10]), "=r"((r)[11]), \
          "=r"((r)[12]), "=r"((r)[13]), "=r"((r)[14]), "=r"((r)[15]), \
          "=r"((r)[16]), "=r"((r)[17]), "=r"((r)[18]), "=r"((r)[19]), \
          "=r"((r)[20]), "=r"((r)[21]), "=r"((r)[22]), "=r"((r)[23]), \
          "=r"((r)[24]), "=r"((r)[25]), "=r"((r)[26]), "=r"((r)[27]), \
          "=r"((r)[28]), "=r"((r)[29]), "=r"((r)[30]), "=r"((r)[31]) \
        : "r"(tma))
static constexpr uint64_t SMEM_DESC_BASE_SW128 =
    (uint64_t(2) << 61) | (uint64_t(1) << 46) | (uint64_t(64) << 32) | (uint64_t(1) << 16);
#define MAKE_SMEM_DESC(ba) (SMEM_DESC_BASE_SW128 | ((uint64_t)((ba) >> 4) & 0x3FFF))
__device__ __forceinline__ void bulk_g2s(uint32_t dst, const void* src, uint32_t bytes, uint32_t mbar) {
    asm volatile("cp.async.bulk.shared::cluster.global.mbarrier::complete_tx::bytes [%0], [%1], %2, [%3];"
        :: "r"(dst), "l"(src), "r"(bytes), "r"(mbar) : "memory");
}
__device__ __forceinline__ void mma_f16_cg1(uint32_t d, uint64_t ad, uint64_t bd, uint32_t idesc, bool en) {
    uint32_t e = en ? 1u : 0u;
    asm volatile("{\n\t.reg .pred p;\n\tsetp.ne.u32 p, %5, 0;\n\t"
        "tcgen05.mma.cta_group::1.kind::f16 [%0], %1, %2, %3, {%4, %4, %4, %4}, p;\n\t}"
        :: "r"(d), "l"(ad), "l"(bd), "r"(idesc), "r"(0u), "r"(e) : "memory");
}
#endif  // USE_TC

// ---------------- elementwise kernels ----------------
__global__ void quant_x_kernel(const float* __restrict__ hs) {
    int idx = blockIdx.x * blockDim.x + threadIdx.x;
    if (idx >= S_LEN * D_DIM) return;
    int q = clampi(__float2int_rn(__fdiv_rn(hs[idx], 0.1f)), -128, 127);
#if USE_TC
    int s = idx >> 12, d = idx & (D_DIM - 1);
    int mt = s >> 7, r = s & 127, kt = d >> 6, c = d & 63;
    *(__nv_bfloat16*)((char*)g_xa + (((size_t)(mt * 64 + kt)) << 14) + sw_off(r, c)) =
        __float2bfloat16_rn((float)q);
#else
    g_x8[idx] = (int8_t)q;
#endif
}

__global__ void convert_w_kernel(const float* __restrict__ wq, const float* __restrict__ wk,
                                 const float* __restrict__ wv, const float* __restrict__ wo) {
    int idx = blockIdx.x * blockDim.x + threadIdx.x;
    int z = blockIdx.y;
    if (idx >= D_DIM * D_DIM) return;
    const float* src = (z == 0) ? wq : (z == 1) ? wk : (z == 2) ? wv : wo;
    int w = (int)__float2int_rn(src[idx]);
#if USE_TC
    int o = idx >> 12, k = idx & (D_DIM - 1);
    int nt = o >> 7, r = o & 127, kt = k >> 6, c = k & 63;
    *(__nv_bfloat16*)((char*)g_wb[z] + (((size_t)(nt * 64 + kt)) << 14) + sw_off(r, c)) =
        __float2bfloat16_rn((float)w);
#else
    g_w8[z][idx] = (int8_t)w;
#endif
}

__global__ void rope_table_kernel(const int* __restrict__ pos) {
    int idx = blockIdx.x * blockDim.x + threadIdx.x;
    if (idx >= S_LEN * 64) return;
    int s = idx >> 6, i = idx & 63;
    float e = (float)(2 * i) * (1.0f / 128.0f);
    float powf32 = (float)pow(10000.0, (double)e);
    float invf = 1.0f / powf32;
    float ang = (float)pos[s] * invf;
    double a = (double)ang;
    g_rope[idx] = make_float2((float)cos(a), (float)sin(a));
}

__global__ void ropequant_kernel(const float* __restrict__ sq, const float* __restrict__ sk,
                                 const float* __restrict__ sv) {
    int idx = blockIdx.x * blockDim.x + threadIdx.x;
    if (idx >= S_LEN * D_DIM) return;
    int s = idx >> 12, o = idx & (D_DIM - 1);
    int h = o >> 7, j = o & 127;
    float2 cs = g_rope[(s << 6) + (j & 63)];
    int o2 = (h << 7) + ((j < 64) ? (j + 64) : (j - 64));
    float sign = (j < 64) ? -1.0f : 1.0f;
    int base = s * D_DIM;
    int dsti = (h * S_LEN + s) * HD + j;
    {
        float a = __fmul_rn((float)g_pint[0][base + o],  __fmul_rn(0.1f, sq[o]));
        float b = __fmul_rn((float)g_pint[0][base + o2], __fmul_rn(0.1f, sq[o2])) * sign;
        float r = __fadd_rn(__fmul_rn(a, cs.x), __fmul_rn(b, cs.y));
        g_q8[dsti] = (int8_t)clampi(__float2int_rn(__fdiv_rn(r, 0.1f)), -128, 127);
    }
    {
        float a = __fmul_rn((float)g_pint[1][base + o],  __fmul_rn(0.1f, sk[o]));
        float b = __fmul_rn((float)g_pint[1][base + o2], __fmul_rn(0.1f, sk[o2])) * sign;
        float r = __fadd_rn(__fmul_rn(a, cs.x), __fmul_rn(b, cs.y));
        g_k8[dsti] = (int8_t)clampi(__float2int_rn(__fdiv_rn(r, 0.1f)), -128, 127);
    }
    {
        float a = __fmul_rn((float)g_pint[2][base + o], __fmul_rn(0.1f, sv[o]));
        int q = clampi(__float2int_rn(__fdiv_rn(a, 0.1f)), -128, 127);
        g_vh[dsti] = __float2half_rn((float)q);
    }
}

__global__ void final_kernel(const float* __restrict__ so, float* __restrict__ out) {
    int idx = blockIdx.x * blockDim.x + threadIdx.x;
    if (idx >= S_LEN * D_DIM) return;
    out[idx] = __fmul_rn((float)g_pint[0][idx], __fmul_rn(0.1f, so[idx & (D_DIM - 1)]));
}

// ---------------- PATH A: legacy wmma int8 GEMM (proven round-2) ----------------
#define GBM 128
#define GBN 128
#define GBK 64
#define GLD 80

__global__ __launch_bounds__(128) void gemm_s8_kernel(int mode) {
#if !USE_TC
    __shared__ __align__(16) int8_t As[2][GBM * GLD];
    __shared__ __align__(16) int8_t Bs[2][GBN * GLD];
    const int8_t* A; const int8_t* B; int* C;
    if (mode == 0) { A = g_x8; B = g_w8[blockIdx.z]; C = g_pint[blockIdx.z]; }
    else           { A = g_oq; B = g_w8[3];          C = g_pint[0]; }
    const int m0 = blockIdx.y * GBM, n0 = blockIdx.x * GBN;
    int tid = threadIdx.x;
    int w = tid >> 5;
    int wm = w & 1, wn = w >> 1;

    wmma::fragment<wmma::accumulator, 16, 16, 16, int> acc[4][4];
    #pragma unroll
    for (int i = 0; i < 4; i++)
        #pragma unroll
        for (int j = 0; j < 4; j++) wmma::fill_fragment(acc[i][j], 0);

    const int KT = KDIM / GBK;
    #pragma unroll
    for (int c = tid; c < 512; c += 128) {
        int r = c >> 2, off = (c & 3) << 4;
        cp_async16(&As[0][r * GLD + off], A + (size_t)(m0 + r) * KDIM + off);
        cp_async16(&Bs[0][r * GLD + off], B + (size_t)(n0 + r) * KDIM + off);
    }
    cp_commit();

    for (int kt = 0; kt < KT; kt++) {
        int buf = kt & 1;
        cp_wait0();
        __syncthreads();
        if (kt + 1 < KT) {
            int k0 = (kt + 1) * GBK;
            #pragma unroll
            for (int c = tid; c < 512; c += 128) {
                int r = c >> 2, off = (c & 3) << 4;
                cp_async16(&As[buf ^ 1][r * GLD + off], A + (size_t)(m0 + r) * KDIM + k0 + off);
                cp_async16(&Bs[buf ^ 1][r * GLD + off], B + (size_t)(n0 + r) * KDIM + k0 + off);
            }
            cp_commit();
        }
        #pragma unroll
        for (int ks = 0; ks < 4; ks++) {
            wmma::fragment<wmma::matrix_a, 16, 16, 16, signed char, wmma::row_major> af[4];
            wmma::fragment<wmma::matrix_b, 16, 16, 16, signed char, wmma::col_major> bf[4];
            #pragma unroll
            for (int i = 0; i < 4; i++)
                wmma::load_matrix_sync(af[i], (const signed char*)&As[buf][(wm * 64 + i * 16) * GLD + ks * 16], GLD);
            #pragma unroll
            for (int j = 0; j < 4; j++)
                wmma::load_matrix_sync(bf[j], (const signed char*)&Bs[buf][(wn * 64 + j * 16) * GLD + ks * 16], GLD);
            #pragma unroll
            for (int i = 0; i < 4; i++)
                #pragma unroll
                for (int j = 0; j < 4; j++)
                    wmma::mma_sync(acc[i][j], af[i], bf[j], acc[i][j]);
        }
        __syncthreads();
    }
    #pragma unroll
    for (int i = 0; i < 4; i++)
        #pragma unroll
        for (int j = 0; j < 4; j++)
            wmma::store_matrix_sync(C + (size_t)(m0 + wm * 64 + i * 16) * D_DIM + (n0 + wn * 64 + j * 16),
                                    acc[i][j], D_DIM, wmma::mem_row_major);
#endif
}

// ---------------- PATH B: tcgen05 bf16 GEMM (M=128, N=128, K-stage 64) ----------------
#define NST 4
#define STG_B 32768
#define T_OFF_TM 0
#define T_OFF_BAR 16
#define T_OFF_DONE 80
#define T_OFF_ST 1024
#define SMEM_TC (T_OFF_ST + NST * STG_B)   // 132096

__global__ __launch_bounds__(128, 1) __cluster_dims__(1, 1, 1) void gemm_tc_kernel(int mode) {
#if USE_TC
    extern __shared__ __align__(1024) char sm[];
    uint32_t sb = smem_u32(sm);
    int tid = threadIdx.x, wid = tid >> 5, lid = tid & 31;

    const char* A; const char* B; int* C;
    if (mode == 0) { A = (const char*)g_xa; B = (const char*)g_wb[blockIdx.z]; C = g_pint[blockIdx.z]; }
    else           { A = (const char*)g_oa; B = (const char*)g_wb[3];          C = g_pint[0]; }
    int mtile = blockIdx.y, ntile = blockIdx.x;

    if (wid == 0) { TCGEN05_ALLOC(sb + T_OFF_TM, 128); TCGEN05_RELINQ(); }
    if (tid == 0) {
        #pragma unroll
        for (int s = 0; s < NST; s++) {
            MBARRIER_INIT(sb + T_OFF_BAR + s * 16, 1);
            MBARRIER_INIT(sb + T_OFF_BAR + s * 16 + 8, 1);
        }
        MBARRIER_INIT(sb + T_OFF_DONE, 1);
    }
    __syncthreads();
    uint32_t tmem;
    asm volatile("ld.shared.b32 %0, [%1];" : "=r"(tmem) : "r"(sb + T_OFF_TM));

    const int KT = KDIM / 64;   // 64 stages of K=64

    if (tid == 0) {
        const char* Ab = A + ((size_t)mtile * 64) * 16384;
        const char* Bb = B + ((size_t)ntile * 64) * 16384;
        for (int kt = 0; kt < KT; kt++) {
            int st = kt & (NST - 1);
            uint32_t fullb = sb + T_OFF_BAR + st * 16;
            uint32_t emptyb = fullb + 8;
            if (kt >= NST) MBARRIER_WAIT_PARITY(emptyb, ((kt >> 2) - 1) & 1);
            MBARRIER_EXPECT_TX(fullb, STG_B);
            uint32_t dst = sb + T_OFF_ST + st * STG_B;
            bulk_g2s(dst,         Ab + (size_t)kt * 16384, 16384, fullb);
            bulk_g2s(dst + 16384, Bb + (size_t)kt * 16384, 16384, fullb);
        }
    } else if (tid == 32) {
        // idesc kind::f16: dtype F32, a/b BF16, N=128 -> 16<<17, M=128 -> 8<<24  (0x8200490)
        const uint32_t idesc = (1u << 4) | (1u << 7) | (1u << 10) | (16u << 17) | (8u << 24);
        for (int kt = 0; kt < KT; kt++) {
            int st = kt & (NST - 1);
            uint32_t fullb = sb + T_OFF_BAR + st * 16;
            uint32_t emptyb = fullb + 8;
            MBARRIER_WAIT_PARITY(fullb, (kt >> 2) & 1);
            uint32_t base = sb + T_OFF_ST + st * STG_B;
            uint64_t ad = MAKE_SMEM_DESC(base);
            uint64_t bd = MAKE_SMEM_DESC(base + 16384);
            #pragma unroll
            for (int sub = 0; sub < 4; sub++)
                mma_f16_cg1(tmem, ad + sub * 2, bd + sub * 2, idesc, (kt > 0) || (sub > 0));
            TCGEN05_COMMIT(emptyb);
        }
        TCGEN05_COMMIT(sb + T_OFF_DONE);
    }

    MBARRIER_WAIT_PARITY(sb + T_OFF_DONE, 0);
    TCGEN05_FENCE_AFTER();

    {
        int* Crow = C + (size_t)(mtile * 128 + wid * 32 + lid) * D_DIM + ntile * 128;
        #pragma unroll
        for (int c0 = 0; c0 < 128; c0 += 32) {
            uint32_t r[32];
            TCGEN05_LD_X32(r, tmem + c0);
            TCGEN05_WAIT_LD();
            #pragma unroll
            for (int j = 0; j < 32; j += 4) {
                int4 v = make_int4(__float2int_rn(__uint_as_float(r[j])),
                                   __float2int_rn(__uint_as_float(r[j + 1])),
                                   __float2int_rn(__uint_as_float(r[j + 2])),
                                   __float2int_rn(__uint_as_float(r[j + 3])));
                *(int4*)(Crow + c0 + j) = v;
            }
        }
    }
    __syncthreads();
    if (wid == 0) TCGEN05_DEALLOC(tmem, 128);
#endif
}

// ---------------- causal flash attention (proven round-2) ----------------
#define QLD 144
#define VLD 136
#define SLD 72
#define OLD 132
#define OFF_Q  0
#define OFF_K  9216
#define OFF_V  18432
#define OFF_SI 35840
#define OFF_PH 54272
#define OFF_PL 63488
#define OFF_O  72704
#define OFF_M  106496
#define OFF_L  106752
#define SMEM_ATTN 107008

__global__ __launch_bounds__(256) void attn_kernel() {
    extern __shared__ __align__(16) char sm[];
    int8_t* Qs = (int8_t*)(sm + OFF_Q);
    int8_t* Ks = (int8_t*)(sm + OFF_K);
    __half* Vs = (__half*)(sm + OFF_V);
    int*    Si = (int*)(sm + OFF_SI);
    __half* Ph = (__half*)(sm + OFF_PH);
    __half* Pl = (__half*)(sm + OFF_PL);
    float*  Os = (float*)(sm + OFF_O);
    float*  m_s = (float*)(sm + OFF_M);
    float*  l_s = (float*)(sm + OFF_L);

    int qtile = gridDim.x - 1 - blockIdx.x;
    int h = blockIdx.y;
    int tid = threadIdx.x;
    int w = tid >> 5;
    const float NEGINF = __int_as_float(0xff800000);

    {
        const int8_t* Qg = g_q8 + (size_t)(h * S_LEN + qtile * 64) * HD;
        #pragma unroll
        for (int c = tid; c < 512; c += 256) {
            int r = c >> 3, off = (c & 7) << 4;
            *(int4*)(Qs + r * QLD + off) = *(const int4*)(Qg + r * HD + off);
        }
    }
    for (int i = tid; i < 64 * OLD; i += 256) Os[i] = 0.0f;
    if (tid < 64) { m_s[tid] = -1e30f; l_s[tid] = 0.0f; }

    int row = tid >> 2;
    int qd  = tid & 3;
    const float SC = (float)((double)0.1f * (double)0.1f / 11.313708498984760390);

    for (int t = 0; t <= qtile; t++) {
        __syncthreads();
        const int8_t* Kg = g_k8 + (size_t)(h * S_LEN + t * 64) * HD;
        #pragma unroll
        for (int c = tid; c < 512; c += 256) {
            int r = c >> 3, off = (c & 7) << 4;
            *(int4*)(Ks + r * QLD + off) = *(const int4*)(Kg + r * HD + off);
        }
        const __half* Vg = g_vh + (size_t)(h * S_LEN + t * 64) * HD;
        #pragma unroll
        for (int c = tid; c < 1024; c += 256) {
            int r = c >> 4, off = (c & 15) << 4;
            *(int4*)((char*)Vs + r * (VLD * 2) + off) = *(const int4*)((const char*)(Vg + r * HD) + off);
        }
        __syncthreads();

        {
            int wm = w & 3;
            int wnb = (w >> 2) << 1;
            wmma::fragment<wmma::accumulator, 16, 16, 16, int> sacc[2];
            wmma::fill_fragment(sacc[0], 0);
            wmma::fill_fragment(sacc[1], 0);
            #pragma unroll
            for (int k = 0; k < 8; k++) {
                wmma::fragment<wmma::matrix_a, 16, 16, 16, signed char, wmma::row_major> aq;
                wmma::load_matrix_sync(aq, (const signed char*)(Qs + (wm * 16) * QLD + k * 16), QLD);
                #pragma unroll
                for (int n = 0; n < 2; n++) {
                    wmma::fragment<wmma::matrix_b, 16, 16, 16, signed char, wmma::col_major> bk;
                    wmma::load_matrix_sync(bk, (const signed char*)(Ks + ((wnb + n) * 16) * QLD + k * 16), QLD);
                    wmma::mma_sync(sacc[n], aq, bk, sacc[n]);
                }
            }
            wmma::store_matrix_sync(Si + (wm * 16) * SLD + wnb * 16,       sacc[0], SLD, wmma::mem_row_major);
            wmma::store_matrix_sync(Si + (wm * 16) * SLD + (wnb + 1) * 16, sacc[1], SLD, wmma::mem_row_major);
        }
        __syncthreads();

        {
            bool diag = (t == qtile);
            float vals[16];
            float mloc = NEGINF;
            #pragma unroll
            for (int jj = 0; jj < 16; jj++) {
                int j = qd * 16 + jj;
                float v = (diag && j > row) ? NEGINF : (float)Si[row * SLD + j] * SC;
                vals[jj] = v;
                mloc = fmaxf(mloc, v);
            }
            mloc = fmaxf(mloc, __shfl_xor_sync(0xffffffffu, mloc, 1));
            mloc = fmaxf(mloc, __shfl_xor_sync(0xffffffffu, mloc, 2));
            float mold = m_s[row];
            float mnew = fmaxf(mold, mloc);
            float alpha = expf(mold - mnew);
            float psum = 0.0f;
            #pragma unroll
            for (int jj = 0; jj < 16; jj++) {
                float p = expf(vals[jj] - mnew);
                psum += p;
                __half ph = __float2half_rn(p);
                Ph[row * SLD + qd * 16 + jj] = ph;
                Pl[row * SLD + qd * 16 + jj] = __float2half_rn(p - __half2float(ph));
            }
            psum += __shfl_xor_sync(0xffffffffu, psum, 1);
            psum += __shfl_xor_sync(0xffffffffu, psum, 2);
            if (qd == 0) {
                m_s[row] = mnew;
                l_s[row] = l_s[row] * alpha + psum;
            }
            if (alpha != 1.0f) {
                #pragma unroll
                for (int c = 0; c < 32; c++)
                    Os[row * OLD + qd * 32 + c] *= alpha;
            }
        }
        __syncthreads();

        {
            int wm = w & 3;
            int wnb = (w >> 2) << 2;
            wmma::fragment<wmma::accumulator, 16, 16, 16, float> oacc[4];
            #pragma unroll
            for (int n = 0; n < 4; n++)
                wmma::load_matrix_sync(oacc[n], Os + (wm * 16) * OLD + (wnb + n) * 16, OLD, wmma::mem_row_major);
            #pragma unroll
            for (int k = 0; k < 4; k++) {
                wmma::fragment<wmma::matrix_a, 16, 16, 16, __half, wmma::row_major> aph, apl;
                wmma::load_matrix_sync(aph, Ph + (wm * 16) * SLD + k * 16, SLD);
                wmma::load_matrix_sync(apl, Pl + (wm * 16) * SLD + k * 16, SLD);
                #pragma unroll
                for (int n = 0; n < 4; n++) {
                    wmma::fragment<wmma::matrix_b, 16, 16, 16, __half, wmma::row_major> bv;
                    wmma::load_matrix_sync(bv, Vs + (k * 16) * VLD + (wnb + n) * 16, VLD);
                    wmma::mma_sync(oacc[n], aph, bv, oacc[n]);
                    wmma::mma_sync(oacc[n], apl, bv, oacc[n]);
                }
            }
            #pragma unroll
            for (int n = 0; n < 4; n++)
                wmma::store_matrix_sync(Os + (wm * 16) * OLD + (wnb + n) * 16, oacc[n], OLD, wmma::mem_row_major);
        }
    }
    __syncthreads();

    // epilogue: quantize (round(x/0.1), clamp -127..127), store for the active o-proj path
    {
        float linv = l_s[row];
        int s_glob = qtile * 64 + row;
        #pragma unroll
        for (int c = 0; c < 32; c++) {
            int col = qd * 32 + c;
            float x = __fmul_rn(__fdiv_rn(Os[row * OLD + col], linv), 0.1f);
            int q = clampi(__float2int_rn(__fdiv_rn(x, 0.1f)), -127, 127);
#if USE_TC
            int mt = s_glob >> 7, r = s_glob & 127;
            int kcol = h * HD + col;
            int ktile = kcol >> 6, cc = kcol & 63;
            *(__nv_bfloat16*)((char*)g_oa + (((size_t)(mt * 64 + ktile)) << 14) + sw_off(r, cc)) =
                __float2bfloat16_rn((float)q);
#else
            g_oq[(size_t)s_glob * D_DIM + h * HD + col] = (int8_t)q;
#endif
        }
    }
}

// ---------------- launch ----------------
extern "C" void kernel_launch(void* const* d_in, const int* in_sizes, int n_in,
                              void* d_out, int out_size) {
    const float* hs = (const float*)d_in[0];
    const float* wq = (const float*)d_in[1];
    const float* wk = (const float*)d_in[2];
    const float* wv = (const float*)d_in[3];
    const float* wo = (const float*)d_in[4];
    const float* sq = (const float*)d_in[5];
    const float* sk = (const float*)d_in[6];
    const float* sv = (const float*)d_in[7];
    const float* so = (const float*)d_in[8];
    const int*   pos = (const int*)d_in[10];
    float* out = (float*)d_out;

    cudaFuncSetAttribute(attn_kernel, cudaFuncAttributeMaxDynamicSharedMemorySize, SMEM_ATTN);
    cudaFuncSetAttribute(gemm_tc_kernel, cudaFuncAttributeMaxDynamicSharedMemorySize, SMEM_TC);

    quant_x_kernel<<<(S_LEN * D_DIM + 255) / 256, 256>>>(hs);
    convert_w_kernel<<<dim3((D_DIM * D_DIM + 255) / 256, 4), 256>>>(wq, wk, wv, wo);
    rope_table_kernel<<<(S_LEN * 64 + 255) / 256, 256>>>(pos);

    // QKV projections — exactly one of these two has a body per compiled arch
    gemm_s8_kernel<<<dim3(D_DIM / GBN, S_LEN / GBM, 3), 128>>>(0);
    gemm_tc_kernel<<<dim3(D_DIM / 128, S_LEN / 128, 3), 128, SMEM_TC>>>(0);

    ropequant_kernel<<<(S_LEN * D_DIM + 255) / 256, 256>>>(sq, sk, sv);

    attn_kernel<<<dim3(S_LEN / 64, H_NUM), 256, SMEM_ATTN>>>();

    // o-proj
    gemm_s8_kernel<<<dim3(D_DIM / GBN, S_LEN / GBM, 1), 128>>>(1);
    gemm_tc_kernel<<<dim3(D_DIM / 128, S_LEN / 128, 1), 128, SMEM_TC>>>(1);

    final_kernel<<<(S_LEN * D_DIM + 255) / 256, 256>>>(so, out);
}

// round 5
// speedup vs baseline: 5.1450x; 1.2442x over previous
#include <cuda_runtime.h>
#include <cuda_fp16.h>
#include <cuda_bf16.h>
#include <mma.h>
#include <math.h>
#include <stdint.h>

using namespace nvcuda;

#define S_LEN 2048
#define D_DIM 4096
#define H_NUM 32
#define HD    128
#define KDIM  4096

// Arch-specific feature gate: tcgen05 only exists under 'a'/'f' targets.
#if defined(__CUDA_ARCH__) && (defined(__CUDA_ARCH_FEAT_SM103_ALL) || defined(__CUDA_ARCH_FEAT_SM100_ALL) || defined(__CUDA_ARCH_SPECIFIC__) || defined(__CUDA_ARCH_FAMILY_SPECIFIC__))
#define USE_TC 1
#else
#define USE_TC 0
#endif

// ---------------- static scratch (allocation-free rule) ----------------
__device__ int8_t g_x8[S_LEN * D_DIM];              // quantized hidden, int8 linear (wmma path)
__device__ int8_t g_w8[4][D_DIM * D_DIM];           // weights int8 linear (wmma path)
__device__ __nv_bfloat16 g_xa[S_LEN * D_DIM];       // quantized hidden, bf16 SW128-tiled (tc path)
__device__ __nv_bfloat16 g_wb[4][D_DIM * D_DIM];    // weights bf16 SW128-tiled (tc path)
__device__ __nv_bfloat16 g_oa[S_LEN * D_DIM];       // attn out bf16 SW128-tiled (tc path)
__device__ int    g_pint[3][S_LEN * D_DIM];         // raw int32 projections; [0] reused for o-proj (wmma path)
__device__ int8_t g_q8[H_NUM * S_LEN * HD];         // roped+quantized Q  [H,S,HD]
__device__ int8_t g_k8[H_NUM * S_LEN * HD];         // roped+quantized K  [H,S,HD]
__device__ __half g_vh[H_NUM * HD * S_LEN];         // quantized V TRANSPOSED [H,HD,S]
__device__ int8_t g_oq[S_LEN * D_DIM];              // quantized attention out [S,D] (wmma path)
__device__ float2 g_rope[S_LEN * 64];               // (cos,sin) table

// ---------------- helpers ----------------
__device__ __forceinline__ void cp_async16(void* smem, const void* gmem) {
    unsigned saddr = (unsigned)__cvta_generic_to_shared(smem);
    asm volatile("cp.async.cg.shared.global [%0], [%1], 16;\n" :: "r"(saddr), "l"(gmem));
}
__device__ __forceinline__ void cp_commit() { asm volatile("cp.async.commit_group;\n"); }
__device__ __forceinline__ void cp_wait0()  { asm volatile("cp.async.wait_group 0;\n"); }
__device__ __forceinline__ int clampi(int v, int lo, int hi) { return max(lo, min(hi, v)); }

// swizzled byte offset inside a [rows x 128B] SW128 tile for (row r, bf16 col c<64)
__device__ __forceinline__ uint32_t sw_off(int r, int c) {
    return (uint32_t)((r * 128 + c * 2) ^ ((r & 7) << 4));
}

// mma.sync wrappers (legal on base arch; used by attention)
__device__ __forceinline__ void imma16832(int* c, const uint32_t* a, uint32_t b0, uint32_t b1) {
    asm volatile("mma.sync.aligned.m16n8k32.row.col.s32.s8.s8.s32 "
        "{%0,%1,%2,%3}, {%4,%5,%6,%7}, {%8,%9}, {%0,%1,%2,%3};"
        : "+r"(c[0]), "+r"(c[1]), "+r"(c[2]), "+r"(c[3])
        : "r"(a[0]), "r"(a[1]), "r"(a[2]), "r"(a[3]), "r"(b0), "r"(b1));
}
__device__ __forceinline__ void hmma16816(float* c, const uint32_t* a, uint32_t b0, uint32_t b1) {
    asm volatile("mma.sync.aligned.m16n8k16.row.col.f32.f16.f16.f32 "
        "{%0,%1,%2,%3}, {%4,%5,%6,%7}, {%8,%9}, {%0,%1,%2,%3};"
        : "+f"(c[0]), "+f"(c[1]), "+f"(c[2]), "+f"(c[3])
        : "r"(a[0]), "r"(a[1]), "r"(a[2]), "r"(a[3]), "r"(b0), "r"(b1));
}
__device__ __forceinline__ void splitpk(float x0, float x1, uint32_t& hi, uint32_t& lo) {
    __half h0 = __float2half_rn(x0), h1 = __float2half_rn(x1);
    __half e0 = __float2half_rn(x0 - __half2float(h0));
    __half e1 = __float2half_rn(x1 - __half2float(h1));
    hi = (uint32_t)__half_as_ushort(h0) | ((uint32_t)__half_as_ushort(h1) << 16);
    lo = (uint32_t)__half_as_ushort(e0) | ((uint32_t)__half_as_ushort(e1) << 16);
}

#if USE_TC
__device__ __forceinline__ uint32_t smem_u32(const void* p) {
    uint32_t a;
    asm("{ .reg .u64 t; cvta.to.shared.u64 t, %1; cvt.u32.u64 %0, t; }" : "=r"(a) : "l"(p));
    return a;
}
#define MBARRIER_INIT(addr, cnt) \
    asm volatile("mbarrier.init.shared.b64 [%0], %1;" :: "r"((uint32_t)(addr)), "r"((uint32_t)(cnt)) : "memory")
#define MBARRIER_EXPECT_TX(addr, bytes) \
    asm volatile("mbarrier.arrive.expect_tx.shared.b64 _, [%0], %1;" :: "r"((uint32_t)(addr)), "r"((uint32_t)(bytes)) : "memory")
#define MBARRIER_WAIT_PARITY(addr, ph) do {                                   \
    uint32_t _m = (uint32_t)(addr); uint32_t _p = (uint32_t)(ph);             \
    asm volatile("{\n\t.reg .pred P1;\n\t"                                    \
        "WL_%=:\n\t"                                                          \
        "mbarrier.try_wait.parity.acquire.cta.shared::cta.b64 P1, [%0], %1, 0x989680;\n\t" \
        "@P1 bra.uni WD_%=;\n\t"                                              \
        "bra.uni WL_%=;\n\t"                                                  \
        "WD_%=:\n\t}"                                                         \
        :: "r"(_m), "r"(_p) : "memory");                                      \
} while (0)
#define TCGEN05_ALLOC(sma, n) \
    asm volatile("tcgen05.alloc.cta_group::1.sync.aligned.shared::cta.b32 [%0], %1;" \
        :: "r"((uint32_t)(sma)), "r"((uint32_t)(n)) : "memory")
#define TCGEN05_DEALLOC(tm, n) \
    asm volatile("tcgen05.dealloc.cta_group::1.sync.aligned.b32 %0, %1;" :: "r"(tm), "r"((uint32_t)(n)))
#define TCGEN05_RELINQ() \
    asm volatile("tcgen05.relinquish_alloc_permit.cta_group::1.sync.aligned;")
#define TCGEN05_COMMIT(mb) \
    asm volatile("tcgen05.commit.cta_group::1.mbarrier::arrive::one.shared::cluster.b64 [%0];" \
        :: "r"((uint32_t)(mb)) : "memory")
#define TCGEN05_FENCE_AFTER() asm volatile("tcgen05.fence::after_thread_sync;" ::: "memory")
#define TCGEN05_WAIT_LD()     asm volatile("tcgen05.wait::ld.sync.aligned;" ::: "memory")
#define TCGEN05_LD_X32(r, tma) \
    asm volatile("tcgen05.ld.sync.aligned.32x32b.x32.b32 " \
        "{%0,%1,%2,%3,%4,%5,%6,%7,%8,%9,%10,%11,%12,%13,%14,%15," \
        "%16,%17,%18,%19,%20,%21,%22,%23,%24,%25,%26,%27,%28,%29,%30,%31}, [%32];" \
        : "=r"((r)[0]), "=r"((r)[1]), "=r"((r)[2]), "=r"((r)[3]),   \
          "=r"((r)[4]), "=r"((r)[5]), "=r"((r)[6]), "=r"((r)[7]),   \
          "=r"((r)[8]), "=r"((r)[9]), "=r"((r)[10]), "=r"((r)[11]), \
          "=r"((r)[12]), "=r"((r)[13]), "=r"((r)[14]), "=r"((r)[15]), \
          "=r"((r)[16]), "=r"((r)[17]), "=r"((r)[18]), "=r"((r)[19]), \
          "=r"((r)[20]), "=r"((r)[21]), "=r"((r)[22]), "=r"((r)[23]), \
          "=r"((r)[24]), "=r"((r)[25]), "=r"((r)[26]), "=r"((r)[27]), \
          "=r"((r)[28]), "=r"((r)[29]), "=r"((r)[30]), "=r"((r)[31]) \
        : "r"(tma))
static constexpr uint64_t SMEM_DESC_BASE_SW128 =
    (uint64_t(2) << 61) | (uint64_t(1) << 46) | (uint64_t(64) << 32) | (uint64_t(1) << 16);
#define MAKE_SMEM_DESC(ba) (SMEM_DESC_BASE_SW128 | ((uint64_t)((ba) >> 4) & 0x3FFF))
__device__ __forceinline__ void bulk_g2s(uint32_t dst, const void* src, uint32_t bytes, uint32_t mbar) {
    asm volatile("cp.async.bulk.shared::cluster.global.mbarrier::complete_tx::bytes [%0], [%1], %2, [%3];"
        :: "r"(dst), "l"(src), "r"(bytes), "r"(mbar) : "memory");
}
__device__ __forceinline__ void mma_f16_cg1(uint32_t d, uint64_t ad, uint64_t bd, uint32_t idesc, bool en) {
    uint32_t e = en ? 1u : 0u;
    asm volatile("{\n\t.reg .pred p;\n\tsetp.ne.u32 p, %5, 0;\n\t"
        "tcgen05.mma.cta_group::1.kind::f16 [%0], %1, %2, %3, {%4, %4, %4, %4}, p;\n\t}"
        :: "r"(d), "l"(ad), "l"(bd), "r"(idesc), "r"(0u), "r"(e) : "memory");
}
#endif  // USE_TC

// ---------------- elementwise kernels ----------------
__global__ void quant_x_kernel(const float* __restrict__ hs) {
    int idx = blockIdx.x * blockDim.x + threadIdx.x;
    if (idx >= S_LEN * D_DIM) return;
    int q = clampi(__float2int_rn(__fdiv_rn(hs[idx], 0.1f)), -128, 127);
#if USE_TC
    int s = idx >> 12, d = idx & (D_DIM - 1);
    int mt = s >> 7, r = s & 127, kt = d >> 6, c = d & 63;
    *(__nv_bfloat16*)((char*)g_xa + (((size_t)(mt * 64 + kt)) << 14) + sw_off(r, c)) =
        __float2bfloat16_rn((float)q);
#else
    g_x8[idx] = (int8_t)q;
#endif
}

__global__ void convert_w_kernel(const float* __restrict__ wq, const float* __restrict__ wk,
                                 const float* __restrict__ wv, const float* __restrict__ wo) {
    int idx = blockIdx.x * blockDim.x + threadIdx.x;
    int z = blockIdx.y;
    if (idx >= D_DIM * D_DIM) return;
    const float* src = (z == 0) ? wq : (z == 1) ? wk : (z == 2) ? wv : wo;
    int w = (int)__float2int_rn(src[idx]);
#if USE_TC
    int o = idx >> 12, k = idx & (D_DIM - 1);
    int nt = o >> 7, r = o & 127, kt = k >> 6, c = k & 63;
    *(__nv_bfloat16*)((char*)g_wb[z] + (((size_t)(nt * 64 + kt)) << 14) + sw_off(r, c)) =
        __float2bfloat16_rn((float)w);
#else
    g_w8[z][idx] = (int8_t)w;
#endif
}

__global__ void rope_table_kernel(const int* __restrict__ pos) {
    int idx = blockIdx.x * blockDim.x + threadIdx.x;
    if (idx >= S_LEN * 64) return;
    int s = idx >> 6, i = idx & 63;
    float e = (float)(2 * i) * (1.0f / 128.0f);
    float powf32 = (float)pow(10000.0, (double)e);
    float invf = 1.0f / powf32;
    float ang = (float)pos[s] * invf;
    double a = (double)ang;
    g_rope[idx] = make_float2((float)cos(a), (float)sin(a));
}

__global__ void ropequant_kernel(const float* __restrict__ sq, const float* __restrict__ sk,
                                 const float* __restrict__ sv) {
    int idx = blockIdx.x * blockDim.x + threadIdx.x;
    if (idx >= S_LEN * D_DIM) return;
    int s = idx >> 12, o = idx & (D_DIM - 1);
    int h = o >> 7, j = o & 127;
    float2 cs = g_rope[(s << 6) + (j & 63)];
    int o2 = (h << 7) + ((j < 64) ? (j + 64) : (j - 64));
    float sign = (j < 64) ? -1.0f : 1.0f;
    int base = s * D_DIM;
    int dsti = (h * S_LEN + s) * HD + j;
    {
        float a = __fmul_rn((float)g_pint[0][base + o],  __fmul_rn(0.1f, sq[o]));
        float b = __fmul_rn((float)g_pint[0][base + o2], __fmul_rn(0.1f, sq[o2])) * sign;
        float r = __fadd_rn(__fmul_rn(a, cs.x), __fmul_rn(b, cs.y));
        g_q8[dsti] = (int8_t)clampi(__float2int_rn(__fdiv_rn(r, 0.1f)), -128, 127);
    }
    {
        float a = __fmul_rn((float)g_pint[1][base + o],  __fmul_rn(0.1f, sk[o]));
        float b = __fmul_rn((float)g_pint[1][base + o2], __fmul_rn(0.1f, sk[o2])) * sign;
        float r = __fadd_rn(__fmul_rn(a, cs.x), __fmul_rn(b, cs.y));
        g_k8[dsti] = (int8_t)clampi(__float2int_rn(__fdiv_rn(r, 0.1f)), -128, 127);
    }
    {
        float a = __fmul_rn((float)g_pint[2][base + o], __fmul_rn(0.1f, sv[o]));
        int q = clampi(__float2int_rn(__fdiv_rn(a, 0.1f)), -128, 127);
        // V stored TRANSPOSED per head: [h][d][s]
        g_vh[((size_t)h * HD + j) * S_LEN + s] = __float2half_rn((float)q);
    }
}

__global__ void final_kernel(const float* __restrict__ so, float* __restrict__ out) {
#if !USE_TC
    int idx = blockIdx.x * blockDim.x + threadIdx.x;
    if (idx >= S_LEN * D_DIM) return;
    out[idx] = __fmul_rn((float)g_pint[0][idx], __fmul_rn(0.1f, so[idx & (D_DIM - 1)]));
#endif
}

// ---------------- PATH A: legacy wmma int8 GEMM (fallback) ----------------
#define GBM 128
#define GBN 128
#define GBK 64
#define GLD 80

__global__ __launch_bounds__(128) void gemm_s8_kernel(int mode) {
#if !USE_TC
    __shared__ __align__(16) int8_t As[2][GBM * GLD];
    __shared__ __align__(16) int8_t Bs[2][GBN * GLD];
    const int8_t* A; const int8_t* B; int* C;
    if (mode == 0) { A = g_x8; B = g_w8[blockIdx.z]; C = g_pint[blockIdx.z]; }
    else           { A = g_oq; B = g_w8[3];          C = g_pint[0]; }
    const int m0 = blockIdx.y * GBM, n0 = blockIdx.x * GBN;
    int tid = threadIdx.x;
    int w = tid >> 5;
    int wm = w & 1, wn = w >> 1;

    wmma::fragment<wmma::accumulator, 16, 16, 16, int> acc[4][4];
    #pragma unroll
    for (int i = 0; i < 4; i++)
        #pragma unroll
        for (int j = 0; j < 4; j++) wmma::fill_fragment(acc[i][j], 0);

    const int KT = KDIM / GBK;
    #pragma unroll
    for (int c = tid; c < 512; c += 128) {
        int r = c >> 2, off = (c & 3) << 4;
        cp_async16(&As[0][r * GLD + off], A + (size_t)(m0 + r) * KDIM + off);
        cp_async16(&Bs[0][r * GLD + off], B + (size_t)(n0 + r) * KDIM + off);
    }
    cp_commit();

    for (int kt = 0; kt < KT; kt++) {
        int buf = kt & 1;
        cp_wait0();
        __syncthreads();
        if (kt + 1 < KT) {
            int k0 = (kt + 1) * GBK;
            #pragma unroll
            for (int c = tid; c < 512; c += 128) {
                int r = c >> 2, off = (c & 3) << 4;
                cp_async16(&As[buf ^ 1][r * GLD + off], A + (size_t)(m0 + r) * KDIM + k0 + off);
                cp_async16(&Bs[buf ^ 1][r * GLD + off], B + (size_t)(n0 + r) * KDIM + k0 + off);
            }
            cp_commit();
        }
        #pragma unroll
        for (int ks = 0; ks < 4; ks++) {
            wmma::fragment<wmma::matrix_a, 16, 16, 16, signed char, wmma::row_major> af[4];
            wmma::fragment<wmma::matrix_b, 16, 16, 16, signed char, wmma::col_major> bf[4];
            #pragma unroll
            for (int i = 0; i < 4; i++)
                wmma::load_matrix_sync(af[i], (const signed char*)&As[buf][(wm * 64 + i * 16) * GLD + ks * 16], GLD);
            #pragma unroll
            for (int j = 0; j < 4; j++)
                wmma::load_matrix_sync(bf[j], (const signed char*)&Bs[buf][(wn * 64 + j * 16) * GLD + ks * 16], GLD);
            #pragma unroll
            for (int i = 0; i < 4; i++)
                #pragma unroll
                for (int j = 0; j < 4; j++)
                    wmma::mma_sync(acc[i][j], af[i], bf[j], acc[i][j]);
        }
        __syncthreads();
    }
    #pragma unroll
    for (int i = 0; i < 4; i++)
        #pragma unroll
        for (int j = 0; j < 4; j++)
            wmma::store_matrix_sync(C + (size_t)(m0 + wm * 64 + i * 16) * D_DIM + (n0 + wn * 64 + j * 16),
                                    acc[i][j], D_DIM, wmma::mem_row_major);
#endif
}

// ---------------- PATH B: tcgen05 bf16 GEMM (M=256 via 2x M128, N=128, K-stage 64) ----------------
#define NST 4
#define STG_B 49152                 // A0 16KB + A1 16KB + B 16KB
#define T_OFF_TM 0
#define T_OFF_BAR 16
#define T_OFF_DONE 80
#define T_OFF_ST 1024
#define SMEM_TC (T_OFF_ST + NST * STG_B)   // 197632

__global__ __launch_bounds__(128, 1) __cluster_dims__(1, 1, 1)
void gemm_tc_kernel(int mode, const float* __restrict__ so, float* __restrict__ out) {
#if USE_TC
    extern __shared__ __align__(1024) char sm[];
    uint32_t sb = smem_u32(sm);
    int tid = threadIdx.x, wid = tid >> 5, lid = tid & 31;

    const char* A; const char* B; int* C;
    if (mode == 0) { A = (const char*)g_xa; B = (const char*)g_wb[blockIdx.z]; C = g_pint[blockIdx.z]; }
    else           { A = (const char*)g_oa; B = (const char*)g_wb[3];          C = g_pint[0]; }
    int my = blockIdx.y, nt = blockIdx.x;

    if (wid == 0) { TCGEN05_ALLOC(sb + T_OFF_TM, 256); TCGEN05_RELINQ(); }
    if (tid == 0) {
        #pragma unroll
        for (int s = 0; s < NST; s++) {
            MBARRIER_INIT(sb + T_OFF_BAR + s * 16, 1);
            MBARRIER_INIT(sb + T_OFF_BAR + s * 16 + 8, 1);
        }
        MBARRIER_INIT(sb + T_OFF_DONE, 1);
    }
    __syncthreads();
    uint32_t tmem;
    asm volatile("ld.shared.b32 %0, [%1];" : "=r"(tmem) : "r"(sb + T_OFF_TM));

    const int KT = KDIM / 64;   // 64 stages of K=64

    if (tid == 0) {
        for (int kt = 0; kt < KT; kt++) {
            int st = kt & (NST - 1);
            uint32_t fullb = sb + T_OFF_BAR + st * 16;
            uint32_t emptyb = fullb + 8;
            if (kt >= NST) MBARRIER_WAIT_PARITY(emptyb, ((kt >> 2) - 1) & 1);
            MBARRIER_EXPECT_TX(fullb, STG_B);
            uint32_t dst = sb + T_OFF_ST + st * STG_B;
            bulk_g2s(dst,         A + ((size_t)((2 * my)     * 64 + kt) << 14), 16384, fullb);
            bulk_g2s(dst + 16384, A + ((size_t)((2 * my + 1) * 64 + kt) << 14), 16384, fullb);
            bulk_g2s(dst + 32768, B + ((size_t)(nt * 64 + kt) << 14),           16384, fullb);
        }
    } else if (tid == 32) {
        // idesc kind::f16: dtype F32, a/b BF16, N=128 -> 16<<17, M=128 -> 8<<24
        const uint32_t idesc = (1u << 4) | (1u << 7) | (1u << 10) | (16u << 17) | (8u << 24);
        for (int kt = 0; kt < KT; kt++) {
            int st = kt & (NST - 1);
            uint32_t fullb = sb + T_OFF_BAR + st * 16;
            uint32_t emptyb = fullb + 8;
            MBARRIER_WAIT_PARITY(fullb, (kt >> 2) & 1);
            uint32_t base = sb + T_OFF_ST + st * STG_B;
            uint64_t a0 = MAKE_SMEM_DESC(base);
            uint64_t a1 = MAKE_SMEM_DESC(base + 16384);
            uint64_t bd = MAKE_SMEM_DESC(base + 32768);
            #pragma unroll
            for (int sub = 0; sub < 4; sub++) {
                bool en = (kt > 0) || (sub > 0);
                mma_f16_cg1(tmem,       a0 + sub * 2, bd + sub * 2, idesc, en);
                mma_f16_cg1(tmem + 128, a1 + sub * 2, bd + sub * 2, idesc, en);
            }
            TCGEN05_COMMIT(emptyb);
        }
        TCGEN05_COMMIT(sb + T_OFF_DONE);
    }

    MBARRIER_WAIT_PARITY(sb + T_OFF_DONE, 0);
    TCGEN05_FENCE_AFTER();

    #pragma unroll
    for (int half = 0; half < 2; half++) {
        int mrow = my * 256 + half * 128 + wid * 32 + lid;
        #pragma unroll
        for (int c0 = 0; c0 < 128; c0 += 32) {
            uint32_t r[32];
            TCGEN05_LD_X32(r, tmem + half * 128 + c0);
            TCGEN05_WAIT_LD();
            if (mode == 0) {
                int* Crow = C + (size_t)mrow * D_DIM + nt * 128;
                #pragma unroll
                for (int j = 0; j < 32; j += 4) {
                    int4 v = make_int4(__float2int_rn(__uint_as_float(r[j])),
                                       __float2int_rn(__uint_as_float(r[j + 1])),
                                       __float2int_rn(__uint_as_float(r[j + 2])),
                                       __float2int_rn(__uint_as_float(r[j + 3])));
                    *(int4*)(Crow + c0 + j) = v;
                }
            } else {
                float* Orow = out + (size_t)mrow * D_DIM + nt * 128;
                #pragma unroll
                for (int j = 0; j < 32; j++) {
                    int col = nt * 128 + c0 + j;
                    Orow[c0 + j] = __fmul_rn(__uint_as_float(r[j]), __fmul_rn(0.1f, so[col]));
                }
            }
        }
    }
    __syncthreads();
    if (wid == 0) TCGEN05_DEALLOC(tmem, 256);
#endif
}

// ---------------- causal flash attention: register FA-2 with mma.sync ----------------
// CTA: 128 q-rows x (loop over 128-kv tiles). 8 warps; warp w owns q-rows [16w,16w+16).
// QK^T: s8 m16n8k32 (exact s32). PV: split-fp16 m16n8k16, fp32 reg accum.
#define KSTR 144      // K tile row stride (128 s8 + pad)
#define VSTR 272      // V^T tile row stride (128 half + pad)
#define ABUF 53248    // per-buffer bytes: 128*144 + 128*272
#define SMEM_ATT (2 * ABUF)

__global__ __launch_bounds__(256, 1) void attn_kernel() {
    extern __shared__ __align__(16) char sm[];
    int qt = (int)gridDim.x - 1 - (int)blockIdx.x;   // heavy tiles first
    int h = blockIdx.y;
    int tid = threadIdx.x, w = tid >> 5, ln = tid & 31;
    int qr = ln >> 2, qc = ln & 3;

    const int8_t* Kg = g_k8 + (size_t)h * S_LEN * HD;
    const char*   Vg = (const char*)(g_vh + (size_t)h * HD * S_LEN);

    // Q a-fragments (resident whole kernel)
    uint32_t qa[4][4];
    {
        const int8_t* Qg = g_q8 + ((size_t)h * S_LEN + qt * 128 + w * 16) * HD;
        #pragma unroll
        for (int ks = 0; ks < 4; ks++) {
            int off = qc * 4 + ks * 32;
            qa[ks][0] = *(const uint32_t*)(Qg + qr * HD + off);
            qa[ks][1] = *(const uint32_t*)(Qg + (qr + 8) * HD + off);
            qa[ks][2] = *(const uint32_t*)(Qg + qr * HD + off + 16);
            qa[ks][3] = *(const uint32_t*)(Qg + (qr + 8) * HD + off + 16);
        }
    }

    float of[16][4];
    #pragma unroll
    for (int i = 0; i < 16; i++) { of[i][0] = of[i][1] = of[i][2] = of[i][3] = 0.0f; }
    float m0 = -INFINITY, m1 = -INFINITY, l0 = 0.0f, l1 = 0.0f;

    // prefetch kt = 0 into buffer 0
    {
        char* Ks = sm; char* Vt = sm + 128 * KSTR;
        for (int c = tid; c < 1024; c += 256)
            cp_async16(Ks + (c >> 3) * KSTR + (c & 7) * 16, Kg + (size_t)(c >> 3) * HD + (c & 7) * 16);
        for (int c = tid; c < 2048; c += 256)
            cp_async16(Vt + (c >> 4) * VSTR + (c & 15) * 16, Vg + ((size_t)(c >> 4) * S_LEN) * 2 + (c & 15) * 16);
        cp_commit();
    }

    const float SC = (float)((double)0.1f * (double)0.1f / 11.313708498984760390);  // 0.01/sqrt(128)

    for (int kt = 0; kt <= qt; kt++) {
        int buf = kt & 1;
        char* Ks = sm + buf * ABUF;
        char* Vt = Ks + 128 * KSTR;
        if (kt < qt) {
            char* Ks2 = sm + (buf ^ 1) * ABUF;
            char* Vt2 = Ks2 + 128 * KSTR;
            const int8_t* Kt = Kg + (size_t)(kt + 1) * 128 * HD;
            const char*   Vs = Vg + (size_t)(kt + 1) * 128 * 2;
            for (int c = tid; c < 1024; c += 256)
                cp_async16(Ks2 + (c >> 3) * KSTR + (c & 7) * 16, Kt + (size_t)(c >> 3) * HD + (c & 7) * 16);
            for (int c = tid; c < 2048; c += 256)
                cp_async16(Vt2 + (c >> 4) * VSTR + (c & 15) * 16, Vs + ((size_t)(c >> 4) * S_LEN) * 2 + (c & 15) * 16);
            cp_commit();
            asm volatile("cp.async.wait_group 1;\n");
        } else {
            asm volatile("cp.async.wait_group 0;\n");
        }
        __syncthreads();

        // ---- S = Q K^T (exact int) ----
        int sc[16][4];
        #pragma unroll
        for (int nf = 0; nf < 16; nf++) { sc[nf][0] = sc[nf][1] = sc[nf][2] = sc[nf][3] = 0; }
        #pragma unroll
        for (int ks = 0; ks < 4; ks++) {
            #pragma unroll
            for (int nf = 0; nf < 16; nf++) {
                const char* bp = Ks + (nf * 8 + qr) * KSTR + qc * 4 + ks * 32;
                uint32_t b0 = *(const uint32_t*)bp;
                uint32_t b1 = *(const uint32_t*)(bp + 16);
                imma16832(sc[nf], qa[ks], b0, b1);
            }
        }

        // ---- online softmax (registers) ----
        float fs[16][4];
        float mx0 = -INFINITY, mx1 = -INFINITY;
        bool diag = (kt == qt);
        #pragma unroll
        for (int nf = 0; nf < 16; nf++) {
            #pragma unroll
            for (int c = 0; c < 4; c++) {
                float v = (float)sc[nf][c] * SC;
                if (diag) {
                    int col = nf * 8 + qc * 2 + (c & 1);
                    int rowl = w * 16 + qr + ((c >> 1) << 3);
                    if (col > rowl) v = -INFINITY;
                }
                fs[nf][c] = v;
                if (c < 2) mx0 = fmaxf(mx0, v); else mx1 = fmaxf(mx1, v);
            }
        }
        mx0 = fmaxf(mx0, __shfl_xor_sync(0xffffffffu, mx0, 1));
        mx0 = fmaxf(mx0, __shfl_xor_sync(0xffffffffu, mx0, 2));
        mx1 = fmaxf(mx1, __shfl_xor_sync(0xffffffffu, mx1, 1));
        mx1 = fmaxf(mx1, __shfl_xor_sync(0xffffffffu, mx1, 2));
        float mn0 = fmaxf(m0, mx0), mn1 = fmaxf(m1, mx1);
        float al0 = expf(m0 - mn0), al1 = expf(m1 - mn1);
        m0 = mn0; m1 = mn1;
        float ps0 = 0.0f, ps1 = 0.0f;
        #pragma unroll
        for (int nf = 0; nf < 16; nf++) {
            float p0 = expf(fs[nf][0] - mn0);
            float p1 = expf(fs[nf][1] - mn0);
            float p2 = expf(fs[nf][2] - mn1);
            float p3 = expf(fs[nf][3] - mn1);
            fs[nf][0] = p0; fs[nf][1] = p1; fs[nf][2] = p2; fs[nf][3] = p3;
            ps0 += p0 + p1; ps1 += p2 + p3;
        }
        ps0 += __shfl_xor_sync(0xffffffffu, ps0, 1);
        ps0 += __shfl_xor_sync(0xffffffffu, ps0, 2);
        ps1 += __shfl_xor_sync(0xffffffffu, ps1, 1);
        ps1 += __shfl_xor_sync(0xffffffffu, ps1, 2);
        l0 = l0 * al0 + ps0;
        l1 = l1 * al1 + ps1;
        #pragma unroll
        for (int nf = 0; nf < 16; nf++) {
            of[nf][0] *= al0; of[nf][1] *= al0; of[nf][2] *= al1; of[nf][3] *= al1;
        }

        // ---- O += (Phi + Plo) * V (split fp16) ----
        #pragma unroll
        for (int ks = 0; ks < 8; ks++) {
            uint32_t ah[4], alr[4];
            splitpk(fs[2 * ks][0],     fs[2 * ks][1],     ah[0], alr[0]);
            splitpk(fs[2 * ks][2],     fs[2 * ks][3],     ah[1], alr[1]);
            splitpk(fs[2 * ks + 1][0], fs[2 * ks + 1][1], ah[2], alr[2]);
            splitpk(fs[2 * ks + 1][2], fs[2 * ks + 1][3], ah[3], alr[3]);
            #pragma unroll
            for (int nf = 0; nf < 16; nf++) {
                const char* vp = Vt + (nf * 8 + qr) * VSTR + qc * 4 + ks * 32;
                uint32_t b0 = *(const uint32_t*)vp;
                uint32_t b1 = *(const uint32_t*)(vp + 16);
                hmma16816(of[nf], ah,  b0, b1);
                hmma16816(of[nf], alr, b0, b1);
            }
        }
        __syncthreads();
    }

    // ---- epilogue: quantize round(x/0.1) clamp -127..127, write for o-proj ----
    {
        int s0 = qt * 128 + w * 16 + qr;
        int s1 = s0 + 8;
        #pragma unroll
        for (int nf = 0; nf < 16; nf++) {
            int colb = nf * 8 + qc * 2;
            float x00 = __fmul_rn(__fdiv_rn(of[nf][0], l0), 0.1f);
            float x01 = __fmul_rn(__fdiv_rn(of[nf][1], l0), 0.1f);
            float x10 = __fmul_rn(__fdiv_rn(of[nf][2], l1), 0.1f);
            float x11 = __fmul_rn(__fdiv_rn(of[nf][3], l1), 0.1f);
            int q00 = clampi(__float2int_rn(__fdiv_rn(x00, 0.1f)), -127, 127);
            int q01 = clampi(__float2int_rn(__fdiv_rn(x01, 0.1f)), -127, 127);
            int q10 = clampi(__float2int_rn(__fdiv_rn(x10, 0.1f)), -127, 127);
            int q11 = clampi(__float2int_rn(__fdiv_rn(x11, 0.1f)), -127, 127);
#if USE_TC
            int kcol = h * HD + colb;
            int ktile = kcol >> 6, cc = kcol & 63;
            uint32_t p0 = (uint32_t)__bfloat16_as_ushort(__float2bfloat16_rn((float)q00)) |
                          ((uint32_t)__bfloat16_as_ushort(__float2bfloat16_rn((float)q01)) << 16);
            uint32_t p1 = (uint32_t)__bfloat16_as_ushort(__float2bfloat16_rn((float)q10)) |
                          ((uint32_t)__bfloat16_as_ushort(__float2bfloat16_rn((float)q11)) << 16);
            *(uint32_t*)((char*)g_oa + (((size_t)((s0 >> 7) * 64 + ktile)) << 14) + sw_off(s0 & 127, cc)) = p0;
            *(uint32_t*)((char*)g_oa + (((size_t)((s1 >> 7) * 64 + ktile)) << 14) + sw_off(s1 & 127, cc)) = p1;
#else
            uint16_t u0 = (uint16_t)((uint8_t)(int8_t)q00 | ((uint16_t)(uint8_t)(int8_t)q01 << 8));
            uint16_t u1 = (uint16_t)((uint8_t)(int8_t)q10 | ((uint16_t)(uint8_t)(int8_t)q11 << 8));
            *(uint16_t*)(g_oq + (size_t)s0 * D_DIM + h * HD + colb) = u0;
            *(uint16_t*)(g_oq + (size_t)s1 * D_DIM + h * HD + colb) = u1;
#endif
        }
    }
}

// ---------------- launch ----------------
extern "C" void kernel_launch(void* const* d_in, const int* in_sizes, int n_in,
                              void* d_out, int out_size) {
    const float* hs = (const float*)d_in[0];
    const float* wq = (const float*)d_in[1];
    const float* wk = (const float*)d_in[2];
    const float* wv = (const float*)d_in[3];
    const float* wo = (const float*)d_in[4];
    const float* sq = (const float*)d_in[5];
    const float* sk = (const float*)d_in[6];
    const float* sv = (const float*)d_in[7];
    const float* so = (const float*)d_in[8];
    const int*   pos = (const int*)d_in[10];
    float* out = (float*)d_out;

    cudaFuncSetAttribute(attn_kernel, cudaFuncAttributeMaxDynamicSharedMemorySize, SMEM_ATT);
    cudaFuncSetAttribute(gemm_tc_kernel, cudaFuncAttributeMaxDynamicSharedMemorySize, SMEM_TC);

    quant_x_kernel<<<(S_LEN * D_DIM + 255) / 256, 256>>>(hs);
    convert_w_kernel<<<dim3((D_DIM * D_DIM + 255) / 256, 4), 256>>>(wq, wk, wv, wo);
    rope_table_kernel<<<(S_LEN * 64 + 255) / 256, 256>>>(pos);

    // QKV projections — exactly one of these two has a body per compiled arch
    gemm_s8_kernel<<<dim3(D_DIM / GBN, S_LEN / GBM, 3), 128>>>(0);
    gemm_tc_kernel<<<dim3(D_DIM / 128, S_LEN / 256, 3), 128, SMEM_TC>>>(0, so, out);

    ropequant_kernel<<<(S_LEN * D_DIM + 255) / 256, 256>>>(sq, sk, sv);

    attn_kernel<<<dim3(S_LEN / 128, H_NUM), 256, SMEM_ATT>>>();

    // o-proj (tc path fuses the output scaling; wmma path uses final_kernel)
    gemm_s8_kernel<<<dim3(D_DIM / GBN, S_LEN / GBM, 1), 128>>>(1);
    gemm_tc_kernel<<<dim3(D_DIM / 128, S_LEN / 256, 1), 128, SMEM_TC>>>(1, so, out);

    final_kernel<<<(S_LEN * D_DIM + 255) / 256, 256>>>(so, out);
}